// round 7
// baseline (speedup 1.0000x reference)
#include <cuda_runtime.h>

// ChamferDistance: B=4, N=M=8192, 3-D Gaussian points.
// Output (float32): [dist1 | dist2 | idx1 | idx2], each B*N.
//
// Bit-exact PRUNED nearest-neighbor search.
// - Both clouds counting-sorted by x-bin (128 bins, width 0.125, exact edges).
// - Per query: stage A evaluates 128 x-nearest refs -> upper bound bd;
//   stage B scans only refs with x in [qx-sqrt(bd), qx+sqrt(bd)] (warp-union,
//   expanded +-1 bin: since d >= rn(dx^2) and edges are exact, every candidate
//   with d <= bd -- including exact ties -- lies inside the scanned range).
// - Distances via packed f32x2 (rn, no FMA), per-lane identical to reference
//   ((dx^2+dy^2)+dz^2). Winner tracked as u64 key (d_bits<<32)|orig_id whose
//   min is order-independent and resolves ties to the LOWEST original index
//   == jnp.argmin first-index semantics. Scatter-order nondeterminism from
//   atomics therefore cannot change the output.

#define BATCH 4
#define NPTS  8192
#define NBINS 128
#define NENT  (NPTS / 2)      // ref pairs per (cloud,b)
#define TPB   128

typedef unsigned long long u64;
typedef unsigned int u32;

// Sorted clouds: {x,y,z, bitcast(orig_id)} per point.
__device__ float4 g_sorted[2][BATCH][NPTS];
// Pair-interleaved negated refs: [e][0]={(-xa,-xb),(-ya,-yb)}, [e][1]={(-za,-zb),(idb<<32|ida)}
__device__ ulonglong2 g_pairs[2][BATCH][NENT][2];
__device__ int g_hist[2][BATCH][NBINS];
__device__ int g_prefix[2][BATCH][NBINS + 1];
__device__ int g_cursor[2][BATCH][NBINS];

__device__ __forceinline__ u64 f2_add(u64 a, u64 b) {
    u64 r; asm("add.rn.f32x2 %0, %1, %2;" : "=l"(r) : "l"(a), "l"(b)); return r;
}
__device__ __forceinline__ u64 f2_mul(u64 a, u64 b) {
    u64 r; asm("mul.rn.f32x2 %0, %1, %2;" : "=l"(r) : "l"(a), "l"(b)); return r;
}
__device__ __forceinline__ u64 f2_pack(float lo, float hi) {
    u64 r; asm("mov.b64 %0, {%1, %2};" : "=l"(r) : "f"(lo), "f"(hi)); return r;
}
__device__ __forceinline__ void f2_unpack(float& lo, float& hi, u64 v) {
    asm("mov.b64 {%0, %1}, %2;" : "=f"(lo), "=f"(hi) : "l"(v));
}

__device__ __forceinline__ int bin_of(float x) {
    int v = (int)floorf((x + 8.0f) * 8.0f);   // width 0.125, exact edges
    return min(max(v, 0), NBINS - 1);
}

// ---- setup: counting sort by x-bin -------------------------------------

__global__ void hist_kernel(const float* __restrict__ xyz1,
                            const float* __restrict__ xyz2) {
    const int b = blockIdx.x, c = blockIdx.y;
    const float* src = c ? xyz2 : xyz1;
    __shared__ int sh[NBINS];
    for (int i = threadIdx.x; i < NBINS; i += blockDim.x) sh[i] = 0;
    __syncthreads();
    for (int i = threadIdx.x; i < NPTS; i += blockDim.x)
        atomicAdd(&sh[bin_of(src[((size_t)b * NPTS + i) * 3])], 1);
    __syncthreads();
    for (int i = threadIdx.x; i < NBINS; i += blockDim.x)
        g_hist[c][b][i] = sh[i];   // one block per (c,b): plain overwrite
}

__global__ void scan_kernel() {
    const int t = threadIdx.x;
    if (t < 8) {
        const int c = t >> 2, b = t & 3;
        int run = 0;
        for (int i = 0; i < NBINS; i++) {
            g_prefix[c][b][i] = run;
            g_cursor[c][b][i] = run;
            run += g_hist[c][b][i];
        }
        g_prefix[c][b][NBINS] = run;   // == NPTS
    }
}

__global__ void scatter_kernel(const float* __restrict__ xyz1,
                               const float* __restrict__ xyz2) {
    const int b = blockIdx.x, c = blockIdx.y;
    const float* src = c ? xyz2 : xyz1;
    for (int i = threadIdx.x; i < NPTS; i += blockDim.x) {
        const float* p = src + ((size_t)b * NPTS + i) * 3;
        const float x = p[0], y = p[1], z = p[2];
        const int pos = atomicAdd(&g_cursor[c][b][bin_of(x)], 1);
        g_sorted[c][b][pos] = make_float4(x, y, z, __int_as_float(i));
    }
}

__global__ void pairs_kernel() {
    const int eg = blockIdx.x * blockDim.x + threadIdx.x;
    if (eg >= 2 * BATCH * NENT) return;
    const int c = eg / (BATCH * NENT);
    const int r = eg - c * (BATCH * NENT);
    const int b = r / NENT;
    const int e = r - b * NENT;
    const float4 s0 = g_sorted[c][b][2 * e];
    const float4 s1 = g_sorted[c][b][2 * e + 1];
    g_pairs[c][b][e][0] = make_ulonglong2(f2_pack(-s0.x, -s1.x),
                                          f2_pack(-s0.y, -s1.y));
    const u64 idp = ((u64)(u32)__float_as_int(s1.w) << 32) |
                    (u32)__float_as_int(s0.w);
    g_pairs[c][b][e][1] = make_ulonglong2(f2_pack(-s0.z, -s1.z), idp);
}

// ---- main: pruned NN ----------------------------------------------------

__global__ void __launch_bounds__(TPB)
chamfer_kernel(float* __restrict__ out) {
    // Block decode: 8 (dir,b) groups x 64 blocks; warps strided across the
    // sorted range (blk + warp*64) so each block mixes dense and sparse work.
    const int db   = blockIdx.x >> 6;           // 0..7
    const int blk  = blockIdx.x & 63;
    const int dir  = db >> 2;
    const int b    = db & 3;
    const int lane = threadIdx.x & 31;
    const int wr   = blk + (threadIdx.x >> 5) * 64;     // warp rank 0..255
    const int qi   = wr * 32 + lane;                    // sorted query index

    const int qc = dir ? 1 : 0;       // query cloud
    const int rc = 1 - qc;            // reference cloud

    const float4 qp = g_sorted[qc][b][qi];
    const int qid = __float_as_int(qp.w);
    const u64 qx2 = f2_pack(qp.x, qp.x);
    const u64 qy2 = f2_pack(qp.y, qp.y);
    const u64 qz2 = f2_pack(qp.z, qp.z);

    const int* __restrict__ P = g_prefix[rc][b];
    const ulonglong2* __restrict__ pr = &g_pairs[rc][b][0][0];

    u64 bkey = 0xFFFFFFFFFFFFFFFFull;

#define EVAL(E)                                                               \
    do {                                                                      \
        const ulonglong2 v0 = pr[2 * (E)];                                    \
        const ulonglong2 v1 = pr[2 * (E) + 1];                                \
        u64 dx = f2_add(qx2, v0.x);                                           \
        u64 dy = f2_add(qy2, v0.y);                                           \
        u64 dz = f2_add(qz2, v1.x);                                           \
        u64 d2 = f2_add(f2_add(f2_mul(dx, dx), f2_mul(dy, dy)),               \
                        f2_mul(dz, dz));                                      \
        float dlo, dhi;                                                       \
        f2_unpack(dlo, dhi, d2);                                              \
        const u64 ka = ((u64)__float_as_uint(dlo) << 32) | (u32)(v1.y);       \
        const u64 kb = ((u64)__float_as_uint(dhi) << 32) | (u32)(v1.y >> 32); \
        if (ka < bkey) bkey = ka;                                             \
        if (kb < bkey) bkey = kb;                                             \
    } while (0)

    // Stage A: 128 x-nearest refs (64 pair entries) -> upper bound bd.
    {
        const int b16 = __shfl_sync(0xFFFFFFFFu, bin_of(qp.x), 16);
        int e0 = P[b16] / 2 - 32;
        e0 = min(max(e0, 0), NENT - 64);
#pragma unroll 4
        for (int e = e0; e < e0 + 64; e++) EVAL(e);
    }

    // Stage B: warp-union window scan.
    {
        const float bd = __uint_as_float((u32)(bkey >> 32));
        const float s = sqrtf(bd);
        float xlo = qp.x - s, xhi = qp.x + s;
#pragma unroll
        for (int o = 16; o; o >>= 1) {
            xlo = fminf(xlo, __shfl_xor_sync(0xFFFFFFFFu, xlo, o));
            xhi = fmaxf(xhi, __shfl_xor_sync(0xFFFFFFFFu, xhi, o));
        }
        const int blo = max(bin_of(xlo) - 1, 0);          // +-1 bin: swallows
        const int bhi = min(bin_of(xhi) + 1, NBINS - 1);  // all fp rounding
        const int lo = P[blo], hi = P[bhi + 1];
        const int elo = lo >> 1, ehi = (hi + 1) >> 1;
#pragma unroll 4
        for (int e = elo; e < ehi; e++) EVAL(e);   // stage-A overlap: idempotent
    }
#undef EVAL

    const int n = BATCH * NPTS;
    const int base = b * NPTS + qid;
    out[dir * n + base]       = __uint_as_float((u32)(bkey >> 32));  // dist
    out[(2 + dir) * n + base] = (float)(u32)(bkey & 0xFFFFFFFFu);    // idx
}

extern "C" void kernel_launch(void* const* d_in, const int* in_sizes, int n_in,
                              void* d_out, int out_size) {
    const float* xyz1 = (const float*)d_in[0];
    const float* xyz2 = (const float*)d_in[1];
    float* out = (float*)d_out;

    dim3 g84(BATCH, 2);
    hist_kernel<<<g84, 256>>>(xyz1, xyz2);
    scan_kernel<<<1, 32>>>();
    scatter_kernel<<<g84, 256>>>(xyz1, xyz2);
    pairs_kernel<<<(2 * BATCH * NENT + 255) / 256, 256>>>();
    chamfer_kernel<<<512, TPB>>>(out);
}

// round 10
// speedup vs baseline: 2.2686x; 2.2686x over previous
#include <cuda_runtime.h>

// ChamferDistance: B=4, N=M=8192, 3-D Gaussian points.
// Output (float32): [dist1 | dist2 | idx1 | idx2], each B*N.
//
// Bit-exact pruned NN search, block-granular skipping.
//  - Counting-sort both clouds by x-bin (exact bin edges, width 0.125).
//  - Stage A: warp-uniform 256 x-near refs per query (broadcast LDG) ->
//    upper bound bd; per-TILE window [min(qx-s),max(qx+s)],
//    s = sqrt(bd)*1.0001+1e-3 (guard >> all fp rounding; d >= rn(dx^2), so
//    every ref with d <= bd -- incl. exact ties -- lies inside the window).
//  - Pass 2: grid (32 qtiles x 16 ref-slices x 8 dir*b). Block exits with INF
//    partials if its slice's x-range (expanded +-1 bin width: sort is only
//    bin-granular) misses the tile window; else dense smem scan (packed
//    f32x2, rn, no FMA -- per-lane identical to reference ((dx^2+dy^2)+dz^2)).
//  - Winner = min over u64 keys (d_bits<<32)|ref_orig_id: order-independent,
//    ties -> lowest original index == jnp.argmin. Output position = QUERY's
//    original id (from g_sorted.w); idx value = ref id from the key.

#define BATCH 4
#define NPTS  8192
#define NBINS 128
#define BINW  0.125f
#define NENT  (NPTS / 2)
#define QTILE 256
#define NTILE (NPTS / QTILE)     // 32
#define JTILE 512
#define NSLICE (NPTS / JTILE)    // 16
#define JENT  (JTILE / 2)        // 256 pair entries per slice
#define TPB   128
#define IPQ   (QTILE / TPB)      // 2
#define KINF  0xFFFFFFFFFFFFFFFFull

typedef unsigned long long u64;
typedef unsigned int u32;

__device__ float4 g_sorted[2][BATCH][NPTS];          // {x,y,z,bitcast(id)}
__device__ ulonglong2 g_pairs[2][BATCH][NENT][2];    // pair-packed negated refs
__device__ int g_hist[2][BATCH][NBINS];
__device__ int g_prefix[2][BATCH][NBINS + 1];
__device__ int g_cursor[2][BATCH][NBINS];
__device__ float2 g_win[8][NTILE];                   // per (dir*b, tile) x-window
__device__ u64 g_akey[8][NPTS];                      // stage-A candidate keys
__device__ u64 g_part[8][NSLICE][NPTS];              // per-slice partial keys

__device__ __forceinline__ u64 f2_add(u64 a, u64 b) {
    u64 r; asm("add.rn.f32x2 %0, %1, %2;" : "=l"(r) : "l"(a), "l"(b)); return r;
}
__device__ __forceinline__ u64 f2_mul(u64 a, u64 b) {
    u64 r; asm("mul.rn.f32x2 %0, %1, %2;" : "=l"(r) : "l"(a), "l"(b)); return r;
}
__device__ __forceinline__ u64 f2_pack(float lo, float hi) {
    u64 r; asm("mov.b64 %0, {%1, %2};" : "=l"(r) : "f"(lo), "f"(hi)); return r;
}
__device__ __forceinline__ void f2_unpack(float& lo, float& hi, u64 v) {
    asm("mov.b64 {%0, %1}, %2;" : "=f"(lo), "=f"(hi) : "l"(v));
}
__device__ __forceinline__ int bin_of(float x) {
    int v = (int)floorf((x + 8.0f) * 8.0f);
    return min(max(v, 0), NBINS - 1);
}
// Evaluate one pair entry (2 refs) for one query; bit-exact reference chain.
__device__ __forceinline__ void eval_entry(u64 qx2, u64 qy2, u64 qz2,
                                           ulonglong2 v0, ulonglong2 v1,
                                           u64& bkey) {
    u64 dx = f2_add(qx2, v0.x);
    u64 dy = f2_add(qy2, v0.y);
    u64 dz = f2_add(qz2, v1.x);
    u64 d2 = f2_add(f2_add(f2_mul(dx, dx), f2_mul(dy, dy)), f2_mul(dz, dz));
    float dlo, dhi;
    f2_unpack(dlo, dhi, d2);
    u64 ka = ((u64)__float_as_uint(dlo) << 32) | (u32)(v1.y);
    u64 kb = ((u64)__float_as_uint(dhi) << 32) | (u32)(v1.y >> 32);
    if (ka < bkey) bkey = ka;
    if (kb < bkey) bkey = kb;
}

// ---- setup: counting sort by x-bin --------------------------------------

__global__ void hist_kernel(const float* __restrict__ xyz1,
                            const float* __restrict__ xyz2) {
    const int b = blockIdx.x, c = blockIdx.y;
    const float* src = c ? xyz2 : xyz1;
    __shared__ int sh[NBINS];
    for (int i = threadIdx.x; i < NBINS; i += blockDim.x) sh[i] = 0;
    __syncthreads();
    for (int i = threadIdx.x; i < NPTS; i += blockDim.x)
        atomicAdd(&sh[bin_of(src[((size_t)b * NPTS + i) * 3])], 1);
    __syncthreads();
    for (int i = threadIdx.x; i < NBINS; i += blockDim.x)
        g_hist[c][b][i] = sh[i];
}

__global__ void scan_kernel() {
    const int t = threadIdx.x;
    if (t < 8) {
        const int c = t >> 2, b = t & 3;
        int run = 0;
        for (int i = 0; i < NBINS; i++) {
            g_prefix[c][b][i] = run;
            g_cursor[c][b][i] = run;
            run += g_hist[c][b][i];
        }
        g_prefix[c][b][NBINS] = run;
    }
}

__global__ void scatter_kernel(const float* __restrict__ xyz1,
                               const float* __restrict__ xyz2) {
    const int b = blockIdx.x, c = blockIdx.y;
    const float* src = c ? xyz2 : xyz1;
    for (int i = threadIdx.x; i < NPTS; i += blockDim.x) {
        const float* p = src + ((size_t)b * NPTS + i) * 3;
        const float x = p[0], y = p[1], z = p[2];
        const int pos = atomicAdd(&g_cursor[c][b][bin_of(x)], 1);
        g_sorted[c][b][pos] = make_float4(x, y, z, __int_as_float(i));
    }
}

__global__ void pairs_kernel() {
    const int eg = blockIdx.x * blockDim.x + threadIdx.x;
    if (eg >= 2 * BATCH * NENT) return;
    const int c = eg / (BATCH * NENT);
    const int r = eg - c * (BATCH * NENT);
    const int b = r / NENT;
    const int e = r - b * NENT;
    const float4 s0 = g_sorted[c][b][2 * e];
    const float4 s1 = g_sorted[c][b][2 * e + 1];
    g_pairs[c][b][e][0] = make_ulonglong2(f2_pack(-s0.x, -s1.x),
                                          f2_pack(-s0.y, -s1.y));
    const u64 idp = ((u64)(u32)__float_as_int(s1.w) << 32) |
                    (u32)__float_as_int(s0.w);
    g_pairs[c][b][e][1] = make_ulonglong2(f2_pack(-s0.z, -s1.z), idp);
}

// ---- stage A: upper bounds + tile windows -------------------------------

__global__ void __launch_bounds__(QTILE)
stageA_kernel() {
    __shared__ float sxl[QTILE], sxh[QTILE];
    const int db = blockIdx.y, tile = blockIdx.x, t = threadIdx.x;
    const int dir = db >> 2, b = db & 3;
    const int qc = dir, rc = 1 - qc;

    const float4 qp = g_sorted[qc][b][tile * QTILE + t];
    const u64 qx2 = f2_pack(qp.x, qp.x);
    const u64 qy2 = f2_pack(qp.y, qp.y);
    const u64 qz2 = f2_pack(qp.z, qp.z);

    // Warp-uniform candidate range (broadcast LDG): refs near lane 16's rank.
    const int myrank = g_prefix[rc][b][bin_of(qp.x)];
    const int r16 = __shfl_sync(0xFFFFFFFFu, myrank, 16);
    const int e0 = min(max((r16 >> 1) - 64, 0), NENT - 128);
    const ulonglong2* __restrict__ pr = &g_pairs[rc][b][0][0];

    u64 bkey = KINF;
#pragma unroll 2
    for (int e = e0; e < e0 + 128; e++)
        eval_entry(qx2, qy2, qz2, pr[2 * e], pr[2 * e + 1], bkey);

    g_akey[db][tile * QTILE + t] = bkey;

    const float bd = __uint_as_float((u32)(bkey >> 32));
    const float s = sqrtf(bd) * 1.0001f + 1e-3f;   // guard >> any fp rounding
    sxl[t] = qp.x - s;
    sxh[t] = qp.x + s;
    __syncthreads();
    for (int o = QTILE / 2; o > 0; o >>= 1) {
        if (t < o) {
            sxl[t] = fminf(sxl[t], sxl[t + o]);
            sxh[t] = fmaxf(sxh[t], sxh[t + o]);
        }
        __syncthreads();
    }
    if (t == 0) g_win[db][tile] = make_float2(sxl[0], sxh[0]);
}

// ---- pass 2: dense scan of active (tile, slice) blocks ------------------

__global__ void __launch_bounds__(TPB)
pass2_kernel() {
    __shared__ __align__(16) ulonglong2 sE[JENT][2];

    const int tile = blockIdx.x, slice = blockIdx.y, db = blockIdx.z;
    const int dir = db >> 2, b = db & 3;
    const int qc = dir, rc = 1 - qc;
    const int t = threadIdx.x;

    u64* part = &g_part[db][slice][tile * QTILE];

    const float2 win = g_win[db][tile];
    // Sort is bin-granular: slice's true x-range can exceed its endpoint
    // values by up to one bin width on each side. Expand by BINW.
    const float sxmin = g_sorted[rc][b][slice * JTILE].x - BINW;
    const float sxmax = g_sorted[rc][b][slice * JTILE + JTILE - 1].x + BINW;
    if (sxmax < win.x || sxmin > win.y) {   // slice cannot contain any NN/tie
#pragma unroll
        for (int k = 0; k < IPQ; k++) part[t + k * TPB] = KINF;
        return;
    }

    // Stage slice entries into smem (512 x 16B).
    const ulonglong2* __restrict__ src = &g_pairs[rc][b][slice * JENT][0];
    for (int i = t; i < 2 * JENT; i += TPB)
        ((ulonglong2*)sE)[i] = src[i];
    __syncthreads();

    u64 qx2[IPQ], qy2[IPQ], qz2[IPQ], bkey[IPQ];
#pragma unroll
    for (int k = 0; k < IPQ; k++) {
        const float4 qp = g_sorted[qc][b][tile * QTILE + t + k * TPB];
        qx2[k] = f2_pack(qp.x, qp.x);
        qy2[k] = f2_pack(qp.y, qp.y);
        qz2[k] = f2_pack(qp.z, qp.z);
        bkey[k] = KINF;
    }

#pragma unroll 2
    for (int e = 0; e < JENT; e++) {
        const ulonglong2 v0 = sE[e][0];
        const ulonglong2 v1 = sE[e][1];
#pragma unroll
        for (int k = 0; k < IPQ; k++)
            eval_entry(qx2[k], qy2[k], qz2[k], v0, v1, bkey[k]);
    }

#pragma unroll
    for (int k = 0; k < IPQ; k++) part[t + k * TPB] = bkey[k];
}

// ---- pack: reduce slices + stage-A key; position = QUERY orig id --------

__global__ void pack_out_kernel(float* __restrict__ out) {
    const int i = blockIdx.x * blockDim.x + threadIdx.x;
    if (i >= 8 * NPTS) return;
    const int db = i >> 13, spos = i & (NPTS - 1);
    const int dir = db >> 2, b = db & 3;
    const int qc = dir;

    u64 best = g_akey[db][spos];
#pragma unroll
    for (int s = 0; s < NSLICE; s++) {
        const u64 k = g_part[db][s][spos];
        best = (k < best) ? k : best;
    }
    const int qid    = __float_as_int(g_sorted[qc][b][spos].w);  // query id
    const int ref_id = (int)(u32)(best & 0xFFFFFFFFu);           // NN's id
    const int n = BATCH * NPTS;
    out[dir * n + b * NPTS + qid]       = __uint_as_float((u32)(best >> 32));
    out[(2 + dir) * n + b * NPTS + qid] = (float)ref_id;
}

extern "C" void kernel_launch(void* const* d_in, const int* in_sizes, int n_in,
                              void* d_out, int out_size) {
    const float* xyz1 = (const float*)d_in[0];
    const float* xyz2 = (const float*)d_in[1];
    float* out = (float*)d_out;

    dim3 g84(BATCH, 2);
    hist_kernel<<<g84, 256>>>(xyz1, xyz2);
    scan_kernel<<<1, 32>>>();
    scatter_kernel<<<g84, 256>>>(xyz1, xyz2);
    pairs_kernel<<<(2 * BATCH * NENT + 255) / 256, 256>>>();
    stageA_kernel<<<dim3(NTILE, 8), QTILE>>>();
    pass2_kernel<<<dim3(NTILE, NSLICE, 8), TPB>>>();
    pack_out_kernel<<<(8 * NPTS + 255) / 256, 256>>>(out);
}

// round 11
// speedup vs baseline: 2.4407x; 1.0758x over previous
#include <cuda_runtime.h>

// ChamferDistance: B=4, N=M=8192, 3-D Gaussian points.
// Output (float32): [dist1 | dist2 | idx1 | idx2], each B*N.
//
// Bit-exact pruned NN search, rank-exact windows, 2 kernels.
//  sort_kernel: per (cloud,b) block: smem hist -> scan -> scatter -> pair-pack.
//  chamfer_main: 1 query/thread, 128-query tiles. Stage A scans a block-
//    uniform entry band around the tile's rank range -> upper bound bd per
//    query. Tile window [min(x-s), max(x+s)], s = sqrt(bd)*1.0001+1e-3
//    (covers all fp rounding: d >= rn(dx^2)). bin_of is monotone, so the
//    rank range [P[bin(wlo)], P[bin(whi)+1]) is a strict superset of all
//    refs with d <= bd, including exact ties. Dense chunked smem scan of
//    that range (minus the already-scanned stage-A band).
//  Distances: packed f32x2 (rn, no FMA), per-lane identical to reference
//    ((dx^2+dy^2)+dz^2). Winner = min u64 key (d_bits<<32)|ref_id:
//    order-independent, ties -> lowest original ref id == jnp.argmin.
//    Hence scatter-order nondeterminism / window over-coverage / stage-A
//    overlap cannot change the output.

#define BATCH 4
#define NPTS  8192
#define NBINS 128
#define NENT  (NPTS / 2)
#define QTILE 128
#define NTILE (NPTS / QTILE)   // 64
#define TPB   128
#define CHUNK 128              // pair entries per smem stage (4 KB)
#define KINF  0xFFFFFFFFFFFFFFFFull

typedef unsigned long long u64;
typedef unsigned int u32;

__device__ float4 g_sorted[2][BATCH][NPTS];        // {x,y,z,bitcast(id)}
__device__ ulonglong2 g_pairs[2][BATCH][NENT][2];  // pair-packed negated refs
__device__ int g_prefix[2][BATCH][NBINS + 1];

__device__ __forceinline__ u64 f2_add(u64 a, u64 b) {
    u64 r; asm("add.rn.f32x2 %0, %1, %2;" : "=l"(r) : "l"(a), "l"(b)); return r;
}
__device__ __forceinline__ u64 f2_mul(u64 a, u64 b) {
    u64 r; asm("mul.rn.f32x2 %0, %1, %2;" : "=l"(r) : "l"(a), "l"(b)); return r;
}
__device__ __forceinline__ u64 f2_pack(float lo, float hi) {
    u64 r; asm("mov.b64 %0, {%1, %2};" : "=l"(r) : "f"(lo), "f"(hi)); return r;
}
__device__ __forceinline__ void f2_unpack(float& lo, float& hi, u64 v) {
    asm("mov.b64 {%0, %1}, %2;" : "=f"(lo), "=f"(hi) : "l"(v));
}
__device__ __forceinline__ int bin_of(float x) {   // weakly monotone in x
    int v = (int)floorf((x + 8.0f) * 8.0f);
    return min(max(v, 0), NBINS - 1);
}
__device__ __forceinline__ void eval_entry(u64 qx2, u64 qy2, u64 qz2,
                                           ulonglong2 v0, ulonglong2 v1,
                                           u64& bkey) {
    u64 dx = f2_add(qx2, v0.x);
    u64 dy = f2_add(qy2, v0.y);
    u64 dz = f2_add(qz2, v1.x);
    u64 d2 = f2_add(f2_add(f2_mul(dx, dx), f2_mul(dy, dy)), f2_mul(dz, dz));
    float dlo, dhi;
    f2_unpack(dlo, dhi, d2);
    u64 ka = ((u64)__float_as_uint(dlo) << 32) | (u32)(v1.y);
    u64 kb = ((u64)__float_as_uint(dhi) << 32) | (u32)(v1.y >> 32);
    if (ka < bkey) bkey = ka;
    if (kb < bkey) bkey = kb;
}

// ---- fused counting sort + pair pack: one block per (cloud, b) ----------

__global__ void __launch_bounds__(512)
sort_kernel(const float* __restrict__ xyz1, const float* __restrict__ xyz2) {
    const int c = blockIdx.x >> 2, b = blockIdx.x & 3;
    const float* src = (c ? xyz2 : xyz1) + (size_t)b * NPTS * 3;
    const int t = threadIdx.x;
    __shared__ int sh[NBINS], scur[NBINS];

    for (int i = t; i < NBINS; i += 512) sh[i] = 0;
    __syncthreads();
    for (int i = t; i < NPTS; i += 512)
        atomicAdd(&sh[bin_of(src[i * 3])], 1);
    __syncthreads();
    if (t == 0) {
        int run = 0;
        for (int i = 0; i < NBINS; i++) {
            scur[i] = run;
            g_prefix[c][b][i] = run;
            run += sh[i];
        }
        g_prefix[c][b][NBINS] = run;   // == NPTS
    }
    __syncthreads();
    for (int i = t; i < NPTS; i += 512) {
        const float x = src[i * 3], y = src[i * 3 + 1], z = src[i * 3 + 2];
        const int pos = atomicAdd(&scur[bin_of(x)], 1);
        g_sorted[c][b][pos] = make_float4(x, y, z, __int_as_float(i));
    }
    __syncthreads();
    for (int e = t; e < NENT; e += 512) {
        const float4 s0 = g_sorted[c][b][2 * e];
        const float4 s1 = g_sorted[c][b][2 * e + 1];
        g_pairs[c][b][e][0] = make_ulonglong2(f2_pack(-s0.x, -s1.x),
                                              f2_pack(-s0.y, -s1.y));
        const u64 idp = ((u64)(u32)__float_as_int(s1.w) << 32) |
                        (u32)__float_as_int(s0.w);
        g_pairs[c][b][e][1] = make_ulonglong2(f2_pack(-s0.z, -s1.z), idp);
    }
}

// ---- main: stage-A bound + rank-exact window scan, direct output --------

__global__ void __launch_bounds__(TPB)
chamfer_main(float* __restrict__ out) {
    __shared__ __align__(16) ulonglong2 sbuf[CHUNK][2];
    __shared__ float rlo[TPB], rhi[TPB];

    const int tile = blockIdx.x, db = blockIdx.y;
    const int dir = db >> 2, b = db & 3;
    const int qc = dir, rc = 1 - qc;
    const int t = threadIdx.x;

    const float4 qp = g_sorted[qc][b][tile * QTILE + t];
    const u64 qx2 = f2_pack(qp.x, qp.x);
    const u64 qy2 = f2_pack(qp.y, qp.y);
    const u64 qz2 = f2_pack(qp.z, qp.z);
    const int* __restrict__ P = g_prefix[rc][b];
    const ulonglong2* __restrict__ pr = &g_pairs[rc][b][0][0];

    u64 bkey = KINF;

    // Chunked block-uniform range scan (lo/hi uniform across the block).
#define SCAN_RANGE(LO, HI)                                                  \
    for (int base = (LO); base < (HI); base += CHUNK) {                     \
        const int m = min(CHUNK, (HI) - base);                              \
        __syncthreads();                                                    \
        if (t < m) {                                                        \
            sbuf[t][0] = pr[2 * (base + t)];                                \
            sbuf[t][1] = pr[2 * (base + t) + 1];                            \
        }                                                                   \
        __syncthreads();                                                    \
        _Pragma("unroll 4")                                                 \
        for (int e = 0; e < m; e++)                                         \
            eval_entry(qx2, qy2, qz2, sbuf[e][0], sbuf[e][1], bkey);        \
    }

    // Tile x-range (sort is only bin-granular, so reduce, don't trust ends).
    rlo[t] = qp.x; rhi[t] = qp.x;
    __syncthreads();
    for (int o = TPB / 2; o > 0; o >>= 1) {
        if (t < o) {
            rlo[t] = fminf(rlo[t], rlo[t + o]);
            rhi[t] = fmaxf(rhi[t], rhi[t + o]);
        }
        __syncthreads();
    }
    const float xmin = rlo[0], xmax = rhi[0];
    __syncthreads();

    // Stage A: band around the tile's ref-rank range -> finite bound per query.
    const int e0 = max(P[bin_of(xmin)] / 2 - 64, 0);
    const int e1 = min(P[bin_of(xmax) + 1] / 2 + 64, NENT);
    SCAN_RANGE(e0, e1)

    // Per-query window, tile union.
    {
        const float bd = __uint_as_float((u32)(bkey >> 32));
        const float s = sqrtf(bd) * 1.0001f + 1e-3f;  // guard >> fp rounding
        __syncthreads();
        rlo[t] = qp.x - s; rhi[t] = qp.x + s;
        __syncthreads();
        for (int o = TPB / 2; o > 0; o >>= 1) {
            if (t < o) {
                rlo[t] = fminf(rlo[t], rlo[t + o]);
                rhi[t] = fmaxf(rhi[t], rhi[t + o]);
            }
            __syncthreads();
        }
    }
    const int blo = bin_of(rlo[0]);
    const int bhi = bin_of(rhi[0]);
    const int elo = P[blo] >> 1;
    const int ehi = (P[bhi + 1] + 1) >> 1;

    // Scan window minus the stage-A band (skipped region always subset of it).
    const int a  = min(max(e0, elo), ehi);
    const int b2 = min(max(e1, elo), ehi);
    SCAN_RANGE(elo, a)
    SCAN_RANGE(b2, ehi)
#undef SCAN_RANGE

    const int qid    = __float_as_int(qp.w);
    const int ref_id = (int)(u32)(bkey & 0xFFFFFFFFu);
    const int n = BATCH * NPTS;
    out[dir * n + b * NPTS + qid]       = __uint_as_float((u32)(bkey >> 32));
    out[(2 + dir) * n + b * NPTS + qid] = (float)ref_id;
}

extern "C" void kernel_launch(void* const* d_in, const int* in_sizes, int n_in,
                              void* d_out, int out_size) {
    const float* xyz1 = (const float*)d_in[0];
    const float* xyz2 = (const float*)d_in[1];
    float* out = (float*)d_out;

    sort_kernel<<<8, 512>>>(xyz1, xyz2);
    chamfer_main<<<dim3(NTILE, 8), TPB>>>(out);
}